// round 14
// baseline (speedup 1.0000x reference)
#include <cuda_runtime.h>
#include <cuda_bf16.h>
#include <cstdint>
#include <math.h>

#define SEQLEN   2048
#define DIM      4096
#define NHEADS   32
#define NKV      8
#define HD       128
#define WINDOW   4096
#define QSTRIDE  (NHEADS * HD)   // 4096
#define KSTRIDE  (NKV * HD)      // 1024
#define NQKV     (QSTRIDE + 2 * KSTRIDE)   // 6144
#define ATT_SCALE 0.08838834764831843f

// ==================== scratch ==============================================
__device__ __nv_bfloat16 g_xh [(size_t)SEQLEN * DIM];
__device__ __nv_bfloat16 g_xl [(size_t)SEQLEN * DIM];
__device__ __nv_bfloat16 g_wh [(size_t)NQKV * DIM];     // wq|wk|wv packed
__device__ __nv_bfloat16 g_wl [(size_t)NQKV * DIM];
__device__ __nv_bfloat16 g_woh[(size_t)DIM * QSTRIDE];
__device__ __nv_bfloat16 g_wol[(size_t)DIM * QSTRIDE];
__device__ __nv_bfloat16 g_aoh[(size_t)SEQLEN * QSTRIDE];
__device__ __nv_bfloat16 g_aol[(size_t)SEQLEN * QSTRIDE];
__device__ __nv_bfloat16 g_qh[(size_t)SEQLEN * QSTRIDE];
__device__ __nv_bfloat16 g_ql[(size_t)SEQLEN * QSTRIDE];
__device__ __nv_bfloat16 g_kh[(size_t)SEQLEN * KSTRIDE];
__device__ __nv_bfloat16 g_kl[(size_t)SEQLEN * KSTRIDE];
__device__ __nv_bfloat16 g_vh[(size_t)SEQLEN * KSTRIDE];
__device__ __nv_bfloat16 g_vl[(size_t)SEQLEN * KSTRIDE];

// ==================== helpers ===============================================
__device__ __forceinline__ void mma16816(float* c, const uint32_t* a,
                                         uint32_t b0, uint32_t b1) {
    asm volatile(
        "mma.sync.aligned.m16n8k16.row.col.f32.bf16.bf16.f32 "
        "{%0,%1,%2,%3}, {%4,%5,%6,%7}, {%8,%9}, {%0,%1,%2,%3};"
        : "+f"(c[0]), "+f"(c[1]), "+f"(c[2]), "+f"(c[3])
        : "r"(a[0]), "r"(a[1]), "r"(a[2]), "r"(a[3]), "r"(b0), "r"(b1));
}
__device__ __forceinline__ void cp_async16(void* smem_dst, const void* gmem_src) {
    uint32_t sa;
    asm("{ .reg .u64 t; cvta.to.shared.u64 t, %1; cvt.u32.u64 %0, t; }"
        : "=r"(sa) : "l"(smem_dst));
    asm volatile("cp.async.cg.shared.global [%0], [%1], 16;" :: "r"(sa), "l"(gmem_src));
}
#define CP_COMMIT() asm volatile("cp.async.commit_group;" ::: "memory")
__device__ __forceinline__ void ldsm_x4_t(uint32_t* r, uint32_t addr) {
    asm volatile("ldmatrix.sync.aligned.m8n8.x4.trans.shared.b16 {%0,%1,%2,%3}, [%4];"
        : "=r"(r[0]), "=r"(r[1]), "=r"(r[2]), "=r"(r[3]) : "r"(addr));
}
__device__ __forceinline__ uint32_t smem_u32(const void* p) {
    uint32_t a;
    asm("{ .reg .u64 t; cvta.to.shared.u64 t, %1; cvt.u32.u64 %0, t; }"
        : "=r"(a) : "l"(p));
    return a;
}
__device__ __forceinline__ uint32_t pack2(float a, float b) {
    __nv_bfloat162 t = __floats2bfloat162_rn(a, b);
    return *(uint32_t*)&t;
}
__device__ __forceinline__ void store_hilo(__nv_bfloat16* H, __nv_bfloat16* L,
                                           size_t off, float a, float b) {
    float ha = __bfloat162float(__float2bfloat16_rn(a));
    float hb = __bfloat162float(__float2bfloat16_rn(b));
    *(uint32_t*)&H[off] = pack2(ha, hb);
    *(uint32_t*)&L[off] = pack2(a - ha, b - hb);
}

// ==================== merged fp32 -> bf16 hi/lo split (all tensors) =========
#define SPLIT_R0 1048576u                     // x
#define SPLIT_R1 (SPLIT_R0 + 2097152u)        // wq
#define SPLIT_R2 (SPLIT_R1 + 524288u)        // wk
#define SPLIT_R3 (SPLIT_R2 + 524288u)        // wv
#define SPLIT_R4 (SPLIT_R3 + 2097152u)        // wo
#define SPLIT_TOTAL SPLIT_R4

__global__ void split_all_kernel(const float* __restrict__ x,
                                 const float* __restrict__ wq,
                                 const float* __restrict__ wk,
                                 const float* __restrict__ wv,
                                 const float* __restrict__ wo,
                                 __nv_bfloat16* __restrict__ xh, __nv_bfloat16* __restrict__ xl,
                                 __nv_bfloat16* __restrict__ wh, __nv_bfloat16* __restrict__ wl,
                                 __nv_bfloat16* __restrict__ woh, __nv_bfloat16* __restrict__ wol)
{
    uint32_t i = blockIdx.x * blockDim.x + threadIdx.x;
    if (i >= SPLIT_TOTAL) return;

    const float* src;
    __nv_bfloat16 *hi, *lo;
    uint32_t j;
    if (i < SPLIT_R0)      { src = x;  hi = xh;  lo = xl;  j = i; }
    else if (i < SPLIT_R1) { src = wq; hi = wh;  lo = wl;  j = i - SPLIT_R0; }
    else if (i < SPLIT_R2) { src = wk; hi = wh + (size_t)QSTRIDE * DIM;
                             lo = wl + (size_t)QSTRIDE * DIM; j = i - SPLIT_R1; }
    else if (i < SPLIT_R3) { src = wv; hi = wh + (size_t)(QSTRIDE + KSTRIDE) * DIM;
                             lo = wl + (size_t)(QSTRIDE + KSTRIDE) * DIM; j = i - SPLIT_R2; }
    else                   { src = wo; hi = woh; lo = wol; j = i - SPLIT_R3; }

    float4 v0 = ((const float4*)src)[2 * (size_t)j];
    float4 v1 = ((const float4*)src)[2 * (size_t)j + 1];
    float f[8] = { v0.x, v0.y, v0.z, v0.w, v1.x, v1.y, v1.z, v1.w };
    uint32_t hw[4], lw[4];
#pragma unroll
    for (int k = 0; k < 4; k++) {
        float h0 = __bfloat162float(__float2bfloat16_rn(f[2 * k]));
        float h1 = __bfloat162float(__float2bfloat16_rn(f[2 * k + 1]));
        hw[k] = pack2(h0, h1);
        lw[k] = pack2(f[2 * k] - h0, f[2 * k + 1] - h1);
    }
    ((uint4*)hi)[j] = make_uint4(hw[0], hw[1], hw[2], hw[3]);
    ((uint4*)lo)[j] = make_uint4(lw[0], lw[1], lw[2], lw[3]);
}

// ==================== HMMA bf16x3 GEMM (64x64 warp tile, BK16 4-stage) ======
// CTA tile 128x256, 8 warps (2x4), BK=16, 4-stage cp.async ring, occ 1.
#define BKP      24                        // padded row length (elems)
#define A_SUB    (128 * BKP * 2)           // 6144 B
#define B_SUB    (256 * BKP * 2)           // 12288 B
#define STAGE_B  (2 * A_SUB + 2 * B_SUB)   // 36864 B
#define NSTAGE   4
#define GSMEM_BYTES (NSTAGE * STAGE_B)     // 147456 B

__global__ __launch_bounds__(256, 1) void gemm_fused(
    const __nv_bfloat16* __restrict__ Ah, const __nv_bfloat16* __restrict__ Al,
    const __nv_bfloat16* __restrict__ Bh, const __nv_bfloat16* __restrict__ Bl,
    float* __restrict__ C,
    const float* __restrict__ cf, const float* __restrict__ sf,
    __nv_bfloat16* __restrict__ Qh, __nv_bfloat16* __restrict__ Ql,
    __nv_bfloat16* __restrict__ Kh, __nv_bfloat16* __restrict__ Kl,
    __nv_bfloat16* __restrict__ Vh, __nv_bfloat16* __restrict__ Vl,
    float* __restrict__ CK, float* __restrict__ CV,
    int N, int K, int mode)
{
    extern __shared__ char sm[];
    const int tid  = threadIdx.x;
    const int wid  = tid >> 5;
    const int lane = tid & 31;
    const int g    = lane >> 2;
    const int tg   = lane & 3;
    const int wm   = wid & 1;        // 2 warp rows x 64
    const int wn   = wid >> 1;       // 4 warp cols x 64
    const int bm   = blockIdx.y << 7;     // 128 rows
    const int bn   = blockIdx.x << 8;     // 256 cols

    // per-stage smem: [Ah | Al | Bh | Bl], rows padded to BKP elems
    auto load_stage = [&](int s, int k0) {
        char* base = sm + s * STAGE_B;
#pragma unroll
        for (int t = 0; t < 6; t++) {
            int id = tid + (t << 8);        // 0..1535 chunks of 16B
            if (id < 512) {
                int sub = id >> 8;          // 0=Ah, 1=Al
                int idx = id & 255;
                int r = idx >> 1, c = idx & 1;
                const __nv_bfloat16* src = (sub ? Al : Ah);
                cp_async16(base + sub * A_SUB + r * (BKP * 2) + c * 16,
                           src + (size_t)(bm + r) * K + k0 + c * 8);
            } else {
                int id2 = id - 512;         // 0..1023
                int sub = id2 >> 9;         // 0=Bh, 1=Bl
                int idx = id2 & 511;
                int r = idx >> 1, c = idx & 1;
                const __nv_bfloat16* src = (sub ? Bl : Bh);
                cp_async16(base + 2 * A_SUB + sub * B_SUB + r * (BKP * 2) + c * 16,
                           src + (size_t)(bn + r) * K + k0 + c * 8);
            }
        }
        CP_COMMIT();
    };

    float acc[4][8][4];
#pragma unroll
    for (int m = 0; m < 4; m++)
#pragma unroll
        for (int n = 0; n < 8; n++)
#pragma unroll
            for (int k = 0; k < 4; k++) acc[m][n][k] = 0.f;

    const int NIT = K >> 4;   // BK = 16
    load_stage(0, 0);
    load_stage(1, 16);
    load_stage(2, 32);

    for (int it = 0; it < NIT; it++) {
        const int rem = NIT - 1 - it;
        if (rem >= 2)      asm volatile("cp.async.wait_group 2;" ::: "memory");
        else if (rem == 1) asm volatile("cp.async.wait_group 1;" ::: "memory");
        else               asm volatile("cp.async.wait_group 0;" ::: "memory");
        __syncthreads();
        if (it + 3 < NIT) load_stage((it + 3) & (NSTAGE - 1), (it + 3) << 4);

        const char* base = sm + (it & (NSTAGE - 1)) * STAGE_B;
        const __nv_bfloat16* Ahs = (const __nv_bfloat16*)base;
        const __nv_bfloat16* Als = (const __nv_bfloat16*)(base + A_SUB);
        const __nv_bfloat16* Bhs = (const __nv_bfloat16*)(base + 2 * A_SUB);
        const __nv_bfloat16* Bls = (const __nv_bfloat16*)(base + 2 * A_SUB + B_SUB);

        uint32_t bh[8][2], bl[8][2];
#pragma unroll
        for (int n = 0; n < 8; n++) {
            int nr = wn * 64 + n * 8 + g;
            bh[n][0] = *(const uint32_t*)&Bhs[nr * BKP + 2 * tg];
            bh[n][1] = *(const uint32_t*)&Bhs[nr * BKP + 8 + 2 * tg];
            bl[n][0] = *(const uint32_t*)&Bls[nr * BKP + 2 * tg];
            bl[n][1] = *(const uint32_t*)&Bls[nr * BKP + 8 + 2 * tg];
        }
#pragma unroll
        for (int m = 0; m < 4; m++) {
            int mr = wm * 64 + m * 16;
            uint32_t ah[4], al[4];
            ah[0] = *(const uint32_t*)&Ahs[(mr + g)     * BKP + 2 * tg];
            ah[1] = *(const uint32_t*)&Ahs[(mr + 8 + g) * BKP + 2 * tg];
            ah[2] = *(const uint32_t*)&Ahs[(mr + g)     * BKP + 8 + 2 * tg];
            ah[3] = *(const uint32_t*)&Ahs[(mr + 8 + g) * BKP + 8 + 2 * tg];
            al[0] = *(const uint32_t*)&Als[(mr + g)     * BKP + 2 * tg];
            al[1] = *(const uint32_t*)&Als[(mr + 8 + g) * BKP + 2 * tg];
            al[2] = *(const uint32_t*)&Als[(mr + g)     * BKP + 8 + 2 * tg];
            al[3] = *(const uint32_t*)&Als[(mr + 8 + g) * BKP + 8 + 2 * tg];
#pragma unroll
            for (int n = 0; n < 8; n++) {
                mma16816(acc[m][n], ah, bh[n][0], bh[n][1]);
                mma16816(acc[m][n], ah, bl[n][0], bl[n][1]);
                mma16816(acc[m][n], al, bh[n][0], bh[n][1]);
            }
        }
    }

    if (mode == 0) {
#pragma unroll
        for (int m = 0; m < 4; m++) {
            int r0 = bm + wm * 64 + m * 16 + g;
#pragma unroll
            for (int n = 0; n < 8; n++) {
                int col = bn + wn * 64 + n * 8 + 2 * tg;
                *(float2*)&C[(size_t)r0 * N + col] =
                    make_float2(acc[m][n][0], acc[m][n][1]);
                *(float2*)&C[(size_t)(r0 + 8) * N + col] =
                    make_float2(acc[m][n][2], acc[m][n][3]);
            }
        }
    } else if (bn < QSTRIDE) {
        // ---- Q region: rope + scale + hi/lo split ----
#pragma unroll
        for (int m = 0; m < 4; m++) {
            int r0 = bm + wm * 64 + m * 16 + g;
#pragma unroll
            for (int n = 0; n < 8; n++) {
                int col = bn + wn * 64 + n * 8 + 2 * tg;
                int d = (col & 127) >> 1;
                float cA = cf[r0 * 64 + d], sA = sf[r0 * 64 + d];
                float u0 = (acc[m][n][0] * cA - acc[m][n][1] * sA) * ATT_SCALE;
                float v0 = (acc[m][n][0] * sA + acc[m][n][1] * cA) * ATT_SCALE;
                store_hilo(Qh, Ql, (size_t)r0 * QSTRIDE + col, u0, v0);
                float cB = cf[(r0 + 8) * 64 + d], sB = sf[(r0 + 8) * 64 + d];
                float u1 = (acc[m][n][2] * cB - acc[m][n][3] * sB) * ATT_SCALE;
                float v1 = (acc[m][n][2] * sB + acc[m][n][3] * cB) * ATT_SCALE;
                store_hilo(Qh, Ql, (size_t)(r0 + 8) * QSTRIDE + col, u1, v1);
            }
        }
    } else if (bn < QSTRIDE + KSTRIDE) {
        // ---- K region: rope + cache + hi/lo split ----
#pragma unroll
        for (int m = 0; m < 4; m++) {
            int r0 = bm + wm * 64 + m * 16 + g;
#pragma unroll
            for (int n = 0; n < 8; n++) {
                int colk = bn - QSTRIDE + wn * 64 + n * 8 + 2 * tg;
                int d = (colk & 127) >> 1;
                float cA = cf[r0 * 64 + d], sA = sf[r0 * 64 + d];
                float u0 = acc[m][n][0] * cA - acc[m][n][1] * sA;
                float v0 = acc[m][n][0] * sA + acc[m][n][1] * cA;
                *(float2*)&CK[(size_t)r0 * KSTRIDE + colk] = make_float2(u0, v0);
                store_hilo(Kh, Kl, (size_t)r0 * KSTRIDE + colk, u0, v0);
                float cB = cf[(r0 + 8) * 64 + d], sB = sf[(r0 + 8) * 64 + d];
                float u1 = acc[m][n][2] * cB - acc[m][n][3] * sB;
                float v1 = acc[m][n][2] * sB + acc[m][n][3] * cB;
                *(float2*)&CK[(size_t)(r0 + 8) * KSTRIDE + colk] = make_float2(u1, v1);
                store_hilo(Kh, Kl, (size_t)(r0 + 8) * KSTRIDE + colk, u1, v1);
            }
        }
    } else {
        // ---- V region: cache + hi/lo split ----
#pragma unroll
        for (int m = 0; m < 4; m++) {
            int r0 = bm + wm * 64 + m * 16 + g;
#pragma unroll
            for (int n = 0; n < 8; n++) {
                int colv = bn - QSTRIDE - KSTRIDE + wn * 64 + n * 8 + 2 * tg;
                *(float2*)&CV[(size_t)r0 * KSTRIDE + colv] =
                    make_float2(acc[m][n][0], acc[m][n][1]);
                store_hilo(Vh, Vl, (size_t)r0 * KSTRIDE + colv,
                           acc[m][n][0], acc[m][n][1]);
                *(float2*)&CV[(size_t)(r0 + 8) * KSTRIDE + colv] =
                    make_float2(acc[m][n][2], acc[m][n][3]);
                store_hilo(Vh, Vl, (size_t)(r0 + 8) * KSTRIDE + colv,
                           acc[m][n][2], acc[m][n][3]);
            }
        }
    }
}

// ==================== cache tail ============================================
__global__ void cache_tail_kernel(const float* __restrict__ cki,
                                  const float* __restrict__ cvi,
                                  float* __restrict__ cko,
                                  float* __restrict__ cvo)
{
    int idx = blockIdx.x * blockDim.x + threadIdx.x;
    if (idx >= (WINDOW - SEQLEN) * KSTRIDE) return;
    size_t off = (size_t)SEQLEN * KSTRIDE + idx;
    cko[off] = cki[off];
    cvo[off] = cvi[off];
}

// ==================== HMMA flash attention (R10-proven version) =============
#define SPAD      136
#define Q_ELEMS   (128 * SPAD)
#define KV_ELEMS  (64 * SPAD)
#define ATT_SMEM  ((2 * Q_ELEMS + 8 * KV_ELEMS) * 2)

__global__ __launch_bounds__(256, 1) void flash_mma(
    const __nv_bfloat16* __restrict__ Qhg, const __nv_bfloat16* __restrict__ Qlg,
    const __nv_bfloat16* __restrict__ Khg, const __nv_bfloat16* __restrict__ Klg,
    const __nv_bfloat16* __restrict__ Vhg, const __nv_bfloat16* __restrict__ Vlg,
    __nv_bfloat16* __restrict__ Ohg, __nv_bfloat16* __restrict__ Olg)
{
    extern __shared__ __nv_bfloat16 sb[];
    const int tid  = threadIdx.x;
    const int wid  = tid >> 5;
    const int lane = tid & 31;
    const int g    = lane >> 2;
    const int tg   = lane & 3;
    const int qb   = (int)(gridDim.x - 1 - blockIdx.x);
    const int h    = blockIdx.y;
    const int kvh  = h >> 2;
    const int q0   = qb << 7;
    const int mr   = wid << 4;

    __nv_bfloat16* Qhs = sb;
    __nv_bfloat16* Qls = sb + Q_ELEMS;
    __nv_bfloat16* KVs = sb + 2 * Q_ELEMS;
    const uint32_t sbase = smem_u32(sb);

    {
        const __nv_bfloat16* gq[2] = { Qhg, Qlg };
#pragma unroll
        for (int i = 0; i < 16; i++) {
            int id  = tid + (i << 8);
            int tsr = id >> 11, idx = id & 2047;
            int r = idx >> 4, c = idx & 15;
            cp_async16(sb + tsr * Q_ELEMS + r * SPAD + c * 8,
                       gq[tsr] + (size_t)(q0 + r) * QSTRIDE + h * HD + c * 8);
        }
        CP_COMMIT();
    }

    const int NT = 2 * qb + 2;
    const __nv_bfloat16* gkv[4] = { Khg, Klg, Vhg, Vlg };
    auto load_kv = [&](int t, int st) {
        __nv_bfloat16* base = KVs + st * 4 * KV_ELEMS;
#pragma unroll
        for (int i = 0; i < 16; i++) {
            int id  = tid + (i << 8);
            int sub = id >> 10, idx = id & 1023;
            int r = idx >> 4, c = idx & 15;
            cp_async16(base + sub * KV_ELEMS + r * SPAD + c * 8,
                       gkv[sub] + (size_t)(t * 64 + r) * KSTRIDE + kvh * HD + c * 8);
        }
        CP_COMMIT();
    };
    load_kv(0, 0);

    float m0 = -1e30f, m1 = -1e30f, l0 = 0.f, l1 = 0.f;
    float o[16][4];
#pragma unroll
    for (int n = 0; n < 16; n++)
#pragma unroll
        for (int c = 0; c < 4; c++) o[n][c] = 0.f;

    for (int t = 0; t < NT; t++) {
        if (t + 1 < NT) {
            load_kv(t + 1, (t + 1) & 1);
            asm volatile("cp.async.wait_group 1;" ::: "memory");
        } else {
            asm volatile("cp.async.wait_group 0;" ::: "memory");
        }
        __syncthreads();

        if (t * 64 <= q0 + mr + 15) {
            const __nv_bfloat16* Khs = KVs + (t & 1) * 4 * KV_ELEMS;
            const __nv_bfloat16* Kls = Khs + KV_ELEMS;
            const uint32_t vh_base = sbase +
                (uint32_t)(2 * Q_ELEMS + (t & 1) * 4 * KV_ELEMS + 2 * KV_ELEMS) * 2;
            const uint32_t vl_base = vh_base + KV_ELEMS * 2;

            float sc[8][4];
#pragma unroll
            for (int n = 0; n < 8; n++)
#pragma unroll
                for (int c = 0; c < 4; c++) sc[n][c] = 0.f;

#pragma unroll
            for (int k = 0; k < 8; k++) {
                int ks = k << 4;
                uint32_t qh[4], ql[4];
                qh[0] = *(const uint32_t*)&Qhs[(mr + g)     * SPAD + ks + 2 * tg];
                qh[1] = *(const uint32_t*)&Qhs[(mr + 8 + g) * SPAD + ks + 2 * tg];
                qh[2] = *(const uint32_t*)&Qhs[(mr + g)     * SPAD + ks + 8 + 2 * tg];
                qh[3] = *(const uint32_t*)&Qhs[(mr + 8 + g) * SPAD + ks + 8 + 2 * tg];
                ql[0] = *(const uint32_t*)&Qls[(mr + g)     * SPAD + ks + 2 * tg];
                ql[1] = *(const uint32_t*)&Qls[(mr + 8 + g) * SPAD + ks + 2 * tg];
                ql[2] = *(const uint32_t*)&Qls[(mr + g)     * SPAD + ks + 8 + 2 * tg];
                ql[3] = *(const uint32_t*)&Qls[(mr + 8 + g) * SPAD + ks + 8 + 2 * tg];
#pragma unroll
                for (int n = 0; n < 8; n++) {
                    uint32_t kh0, kh1, kl0, kl1;
                    kh0 = *(const uint32_t*)&Khs[(8 * n + g) * SPAD + ks + 2 * tg];
                    kh1 = *(const uint32_t*)&Khs[(8 * n + g) * SPAD + ks + 8 + 2 * tg];
                    kl0 = *(const uint32_t*)&Kls[(8 * n + g) * SPAD + ks + 2 * tg];
                    kl1 = *(const uint32_t*)&Kls[(8 * n + g) * SPAD + ks + 8 + 2 * tg];
                    mma16816(sc[n], qh, kh0, kh1);
                    mma16816(sc[n], qh, kl0, kl1);
                    mma16816(sc[n], ql, kh0, kh1);
                }
            }

            const int qi0 = q0 + mr + g, qi1 = qi0 + 8;
            if (t * 64 + 63 > q0 + mr) {
#pragma unroll
                for (int n = 0; n < 8; n++) {
                    int kj = t * 64 + 8 * n + 2 * tg;
                    if (kj     > qi0) sc[n][0] = -1e30f;
                    if (kj + 1 > qi0) sc[n][1] = -1e30f;
                    if (kj     > qi1) sc[n][2] = -1e30f;
                    if (kj + 1 > qi1) sc[n][3] = -1e30f;
                }
            }

            float mt0 = -1e30f, mt1 = -1e30f;
#pragma unroll
            for (int n = 0; n < 8; n++) {
                mt0 = fmaxf(mt0, fmaxf(sc[n][0], sc[n][1]));
                mt1 = fmaxf(mt1, fmaxf(sc[n][2], sc[n][3]));
            }
            mt0 = fmaxf(mt0, __shfl_xor_sync(0xffffffffu, mt0, 1));
            mt0 = fmaxf(mt0, __shfl_xor_sync(0xffffffffu, mt0, 2));
            mt1 = fmaxf(mt1, __shfl_xor_sync(0xffffffffu, mt1, 1));
            mt1 = fmaxf(mt1, __shfl_xor_sync(0xffffffffu, mt1, 2));
            float m0n = fmaxf(m0, mt0), m1n = fmaxf(m1, mt1);
            float c0 = __expf(m0 - m0n), c1 = __expf(m1 - m1n);
            float rs0 = 0.f, rs1 = 0.f;
#pragma unroll
            for (int n = 0; n < 8; n++) {
                sc[n][0] = __expf(sc[n][0] - m0n);
                sc[n][1] = __expf(sc[n][1] - m0n);
                sc[n][2] = __expf(sc[n][2] - m1n);
                sc[n][3] = __expf(sc[n][3] - m1n);
                rs0 += sc[n][0] + sc[n][1];
                rs1 += sc[n][2] + sc[n][3];
            }
            rs0 += __shfl_xor_sync(0xffffffffu, rs0, 1);
            rs0 += __shfl_xor_sync(0xffffffffu, rs0, 2);
            rs1 += __shfl_xor_sync(0xffffffffu, rs1, 1);
            rs1 += __shfl_xor_sync(0xffffffffu, rs1, 2);
            l0 = l0 * c0 + rs0;
            l1 = l1 * c1 + rs1;
            m0 = m0n; m1 = m1n;
#pragma unroll
            for (int n = 0; n < 16; n++) {
                o[n][0] *= c0; o[n][1] *= c0; o[n][2] *= c1; o[n][3] *= c1;
            }

            uint32_t ph[4][4], pl[4][4];
#pragma unroll
            for (int j = 0; j < 4; j++) {
                const float* A = sc[2 * j];
                const float* B = sc[2 * j + 1];
                float ah0 = __bfloat162float(__float2bfloat16_rn(A[0]));
                float ah1 = __bfloat162float(__float2bfloat16_rn(A[1]));
                float ah2 = __bfloat162float(__float2bfloat16_rn(A[2]));
                float ah3 = __bfloat162float(__float2bfloat16_rn(A[3]));
                float bh0 = __bfloat162float(__float2bfloat16_rn(B[0]));
                float bh1 = __bfloat162float(__float2bfloat16_rn(B[1]));
                float bh2 = __bfloat162float(__float2bfloat16_rn(B[2]));
                float bh3 = __bfloat162float(__float2bfloat16_rn(B[3]));
                ph[j][0] = pack2(ah0, ah1);
                ph[j][1] = pack2(ah2, ah3);
                ph[j][2] = pack2(bh0, bh1);
                ph[j][3] = pack2(bh2, bh3);
                pl[j][0] = pack2(A[0] - ah0, A[1] - ah1);
                pl[j][1] = pack2(A[2] - ah2, A[3] - ah3);
                pl[j][2] = pack2(B[0] - bh0, B[1] - bh1);
                pl[j][3] = pack2(B[2] - bh2, B[3] - bh3);
            }

            const uint32_t va = (uint32_t)(((lane & 15) * SPAD + ((lane >> 4) << 3)) * 2);
#pragma unroll
            for (int j = 0; j < 4; j++) {
                const uint32_t kvoff = va + (uint32_t)(16 * j * SPAD * 2);
#pragma unroll
                for (int u = 0; u < 8; u++) {
                    uint32_t vh[4], vl[4];
                    ldsm_x4_t(vh, vh_base + kvoff + u * 32);
                    ldsm_x4_t(vl, vl_base + kvoff + u * 32);
                    mma16816(o[2 * u],     ph[j], vh[0], vh[1]);
                    mma16816(o[2 * u],     ph[j], vl[0], vl[1]);
                    mma16816(o[2 * u],     pl[j], vh[0], vh[1]);
                    mma16816(o[2 * u + 1], ph[j], vh[2], vh[3]);
                    mma16816(o[2 * u + 1], ph[j], vl[2], vl[3]);
                    mma16816(o[2 * u + 1], pl[j], vh[2], vh[3]);
                }
            }
        }
        __syncthreads();
    }

    const float inv0 = 1.f / l0, inv1 = 1.f / l1;
    const int row0 = q0 + mr + g, row1 = row0 + 8;
#pragma unroll
    for (int n = 0; n < 16; n++) {
        int col = h * HD + 8 * n + 2 * tg;
        float f00 = o[n][0] * inv0, f01 = o[n][1] * inv0;
        float f10 = o[n][2] * inv1, f11 = o[n][3] * inv1;
        store_hilo(Ohg, Olg, (size_t)row0 * QSTRIDE + col, f00, f01);
        store_hilo(Ohg, Olg, (size_t)row1 * QSTRIDE + col, f10, f11);
    }
}

// ==================== launch ================================================
extern "C" void kernel_launch(void* const* d_in, const int* in_sizes, int n_in,
                              void* d_out, int out_size)
{
    (void)in_sizes; (void)n_in; (void)out_size;
    const float* x   = (const float*)d_in[0];
    const float* cf  = (const float*)d_in[1];
    const float* sf  = (const float*)d_in[2];
    const float* cki = (const float*)d_in[5];
    const float* cvi = (const float*)d_in[6];
    const float* wq  = (const float*)d_in[7];
    const float* wk  = (const float*)d_in[8];
    const float* wv  = (const float*)d_in[9];
    const float* wo  = (const float*)d_in[10];

    float* out    = (float*)d_out;
    float* out_ck = out + (size_t)SEQLEN * DIM;
    float* out_cv = out_ck + (size_t)WINDOW * KSTRIDE;

    __nv_bfloat16 *xh, *xl, *wh, *wl, *woh, *wol, *aoh, *aol;
    __nv_bfloat16 *qh, *ql, *kh, *kl, *vh, *vl;
    cudaGetSymbolAddress((void**)&xh,  g_xh);
    cudaGetSymbolAddress((void**)&xl,  g_xl);
    cudaGetSymbolAddress((void**)&wh,  g_wh);
    cudaGetSymbolAddress((void**)&wl,  g_wl);
    cudaGetSymbolAddress((void**)&woh, g_woh);
    cudaGetSymbolAddress((void**)&wol, g_wol);
    cudaGetSymbolAddress((void**)&aoh, g_aoh);
    cudaGetSymbolAddress((void**)&aol, g_aol);
    cudaGetSymbolAddress((void**)&qh,  g_qh);
    cudaGetSymbolAddress((void**)&ql,  g_ql);
    cudaGetSymbolAddress((void**)&kh,  g_kh);
    cudaGetSymbolAddress((void**)&kl,  g_kl);
    cudaGetSymbolAddress((void**)&vh,  g_vh);
    cudaGetSymbolAddress((void**)&vl,  g_vl);

    cudaFuncSetAttribute(gemm_fused,
                         cudaFuncAttributeMaxDynamicSharedMemorySize, GSMEM_BYTES);
    cudaFuncSetAttribute(flash_mma,
                         cudaFuncAttributeMaxDynamicSharedMemorySize, ATT_SMEM);

    // merged splits: x, wq|wk|wv (packed), wo
    split_all_kernel<<<(SPLIT_TOTAL + 255) / 256, 256>>>(
        x, wq, wk, wv, wo, xh, xl, wh, wl, woh, wol);

    // fused QKV projection + rope + split + cache head (CTA tile 128x256)
    gemm_fused<<<dim3(NQKV / 256, SEQLEN / 128), 256, GSMEM_BYTES>>>(
        xh, xl, wh, wl, nullptr, cf, sf,
        qh, ql, kh, kl, vh, vl, out_ck, out_cv, NQKV, DIM, 1);

    cache_tail_kernel<<<((WINDOW - SEQLEN) * KSTRIDE) / 256, 256>>>(cki, cvi, out_ck, out_cv);

    // flash attention (R10-proven)
    flash_mma<<<dim3(SEQLEN / 128, NHEADS), 256, ATT_SMEM>>>(qh, ql, kh, kl, vh, vl, aoh, aol);

    // output projection
    gemm_fused<<<dim3(DIM / 256, SEQLEN / 128), 256, GSMEM_BYTES>>>(
        aoh, aol, woh, wol, out, nullptr, nullptr,
        nullptr, nullptr, nullptr, nullptr, nullptr, nullptr,
        nullptr, nullptr, DIM, DIM, 0);
}

// round 15
// speedup vs baseline: 1.7563x; 1.7563x over previous
#include <cuda_runtime.h>
#include <cuda_bf16.h>
#include <cstdint>
#include <math.h>

#define SEQLEN   2048
#define DIM      4096
#define NHEADS   32
#define NKV      8
#define HD       128
#define WINDOW   4096
#define QSTRIDE  (NHEADS * HD)   // 4096
#define KSTRIDE  (NKV * HD)      // 1024
#define NQKV     (QSTRIDE + 2 * KSTRIDE)   // 6144
#define ATT_SCALE 0.08838834764831843f

// ==================== scratch ==============================================
__device__ __nv_bfloat16 g_xh [(size_t)SEQLEN * DIM];
__device__ __nv_bfloat16 g_xl [(size_t)SEQLEN * DIM];
__device__ __nv_bfloat16 g_wh [(size_t)NQKV * DIM];     // wq|wk|wv packed
__device__ __nv_bfloat16 g_wl [(size_t)NQKV * DIM];
__device__ __nv_bfloat16 g_woh[(size_t)DIM * QSTRIDE];
__device__ __nv_bfloat16 g_wol[(size_t)DIM * QSTRIDE];
__device__ __nv_bfloat16 g_aoh[(size_t)SEQLEN * QSTRIDE];
__device__ __nv_bfloat16 g_aol[(size_t)SEQLEN * QSTRIDE];
__device__ __nv_bfloat16 g_qh[(size_t)SEQLEN * QSTRIDE];
__device__ __nv_bfloat16 g_ql[(size_t)SEQLEN * QSTRIDE];
__device__ __nv_bfloat16 g_kh[(size_t)SEQLEN * KSTRIDE];
__device__ __nv_bfloat16 g_kl[(size_t)SEQLEN * KSTRIDE];
__device__ __nv_bfloat16 g_vh[(size_t)SEQLEN * KSTRIDE];
__device__ __nv_bfloat16 g_vl[(size_t)SEQLEN * KSTRIDE];

// ==================== helpers ===============================================
__device__ __forceinline__ void mma16816(float* c, const uint32_t* a,
                                         uint32_t b0, uint32_t b1) {
    asm volatile(
        "mma.sync.aligned.m16n8k16.row.col.f32.bf16.bf16.f32 "
        "{%0,%1,%2,%3}, {%4,%5,%6,%7}, {%8,%9}, {%0,%1,%2,%3};"
        : "+f"(c[0]), "+f"(c[1]), "+f"(c[2]), "+f"(c[3])
        : "r"(a[0]), "r"(a[1]), "r"(a[2]), "r"(a[3]), "r"(b0), "r"(b1));
}
__device__ __forceinline__ void cp_async16(void* smem_dst, const void* gmem_src) {
    uint32_t sa;
    asm("{ .reg .u64 t; cvta.to.shared.u64 t, %1; cvt.u32.u64 %0, t; }"
        : "=r"(sa) : "l"(smem_dst));
    asm volatile("cp.async.cg.shared.global [%0], [%1], 16;" :: "r"(sa), "l"(gmem_src));
}
#define CP_COMMIT() asm volatile("cp.async.commit_group;" ::: "memory")
__device__ __forceinline__ void ldsm_x4_t(uint32_t* r, uint32_t addr) {
    asm volatile("ldmatrix.sync.aligned.m8n8.x4.trans.shared.b16 {%0,%1,%2,%3}, [%4];"
        : "=r"(r[0]), "=r"(r[1]), "=r"(r[2]), "=r"(r[3]) : "r"(addr));
}
__device__ __forceinline__ uint32_t smem_u32(const void* p) {
    uint32_t a;
    asm("{ .reg .u64 t; cvta.to.shared.u64 t, %1; cvt.u32.u64 %0, t; }"
        : "=r"(a) : "l"(p));
    return a;
}
__device__ __forceinline__ uint32_t pack2(float a, float b) {
    __nv_bfloat162 t = __floats2bfloat162_rn(a, b);
    return *(uint32_t*)&t;
}
__device__ __forceinline__ void store_hilo(__nv_bfloat16* H, __nv_bfloat16* L,
                                           size_t off, float a, float b) {
    float ha = __bfloat162float(__float2bfloat16_rn(a));
    float hb = __bfloat162float(__float2bfloat16_rn(b));
    *(uint32_t*)&H[off] = pack2(ha, hb);
    *(uint32_t*)&L[off] = pack2(a - ha, b - hb);
}

// ==================== merged fp32 -> bf16 hi/lo split (all tensors) =========
#define SPLIT_R0 1048576u                     // x
#define SPLIT_R1 (SPLIT_R0 + 2097152u)        // wq
#define SPLIT_R2 (SPLIT_R1 + 524288u)         // wk
#define SPLIT_R3 (SPLIT_R2 + 524288u)         // wv
#define SPLIT_R4 (SPLIT_R3 + 2097152u)        // wo
#define SPLIT_TOTAL SPLIT_R4

__global__ void split_all_kernel(const float* __restrict__ x,
                                 const float* __restrict__ wq,
                                 const float* __restrict__ wk,
                                 const float* __restrict__ wv,
                                 const float* __restrict__ wo,
                                 __nv_bfloat16* __restrict__ xh, __nv_bfloat16* __restrict__ xl,
                                 __nv_bfloat16* __restrict__ wh, __nv_bfloat16* __restrict__ wl,
                                 __nv_bfloat16* __restrict__ woh, __nv_bfloat16* __restrict__ wol)
{
    uint32_t i = blockIdx.x * blockDim.x + threadIdx.x;
    if (i >= SPLIT_TOTAL) return;

    const float* src;
    __nv_bfloat16 *hi, *lo;
    uint32_t j;
    if (i < SPLIT_R0)      { src = x;  hi = xh;  lo = xl;  j = i; }
    else if (i < SPLIT_R1) { src = wq; hi = wh;  lo = wl;  j = i - SPLIT_R0; }
    else if (i < SPLIT_R2) { src = wk; hi = wh + (size_t)QSTRIDE * DIM;
                             lo = wl + (size_t)QSTRIDE * DIM; j = i - SPLIT_R1; }
    else if (i < SPLIT_R3) { src = wv; hi = wh + (size_t)(QSTRIDE + KSTRIDE) * DIM;
                             lo = wl + (size_t)(QSTRIDE + KSTRIDE) * DIM; j = i - SPLIT_R2; }
    else                   { src = wo; hi = woh; lo = wol; j = i - SPLIT_R3; }

    float4 v0 = ((const float4*)src)[2 * (size_t)j];
    float4 v1 = ((const float4*)src)[2 * (size_t)j + 1];
    float f[8] = { v0.x, v0.y, v0.z, v0.w, v1.x, v1.y, v1.z, v1.w };
    uint32_t hw[4], lw[4];
#pragma unroll
    for (int k = 0; k < 4; k++) {
        float h0 = __bfloat162float(__float2bfloat16_rn(f[2 * k]));
        float h1 = __bfloat162float(__float2bfloat16_rn(f[2 * k + 1]));
        hw[k] = pack2(h0, h1);
        lw[k] = pack2(f[2 * k] - h0, f[2 * k + 1] - h1);
    }
    ((uint4*)hi)[j] = make_uint4(hw[0], hw[1], hw[2], hw[3]);
    ((uint4*)lo)[j] = make_uint4(lw[0], lw[1], lw[2], lw[3]);
}

// ==================== HMMA bf16x3 GEMM (64x64 warp tile, BK32, 3-stage) =====
// CTA tile 128x256, 8 warps (2x4), BK=32, 3-stage cp.async ring, occ 1.
#define GPAD     40
#define A_SUB    10240                 // 128 rows x 80 B
#define B_SUB    20480                 // 256 rows x 80 B
#define STAGE_B  (2 * A_SUB + 2 * B_SUB)   // 61440
#define NSTAGE   3
#define GSMEM_BYTES (NSTAGE * STAGE_B)     // 184320

__global__ __launch_bounds__(256, 1) void gemm_fused(
    const __nv_bfloat16* __restrict__ Ah, const __nv_bfloat16* __restrict__ Al,
    const __nv_bfloat16* __restrict__ Bh, const __nv_bfloat16* __restrict__ Bl,
    float* __restrict__ C,
    const float* __restrict__ cf, const float* __restrict__ sf,
    __nv_bfloat16* __restrict__ Qh, __nv_bfloat16* __restrict__ Ql,
    __nv_bfloat16* __restrict__ Kh, __nv_bfloat16* __restrict__ Kl,
    __nv_bfloat16* __restrict__ Vh, __nv_bfloat16* __restrict__ Vl,
    float* __restrict__ CK, float* __restrict__ CV,
    int N, int K, int mode)
{
    extern __shared__ char sm[];
    const int tid  = threadIdx.x;
    const int wid  = tid >> 5;
    const int lane = tid & 31;
    const int g    = lane >> 2;
    const int tg   = lane & 3;
    const int wm   = wid & 1;        // 2 warp rows x 64
    const int wn   = wid >> 1;       // 4 warp cols x 64
    const int bm   = blockIdx.y << 7;     // 128 rows
    const int bn   = blockIdx.x << 8;     // 256 cols

    // smem layout per stage: [Ah|Al|Bh|Bl]  (R13 load pattern, BK=32)
    auto load_stage = [&](int s, int k0) {
        char* base = sm + s * STAGE_B;
#pragma unroll
        for (int t = 0; t < 12; t++) {
            int id = tid + (t << 8);       // 0..3071 chunks of 16B
            if (id < 1024) {
                int sub = id >> 9;         // 0=Ah, 1=Al
                int idx = id & 511;
                int r = idx >> 2, c = idx & 3;
                const __nv_bfloat16* src = (sub ? Al : Ah);
                cp_async16(base + sub * A_SUB + r * 80 + c * 16,
                           src + (size_t)(bm + r) * K + k0 + c * 8);
            } else {
                int sub = (id - 1024) >> 10;  // 0=Bh, 1=Bl
                int idx = (id - 1024) & 1023;
                int r = idx >> 2, c = idx & 3;
                const __nv_bfloat16* src = (sub ? Bl : Bh);
                cp_async16(base + 2 * A_SUB + sub * B_SUB + r * 80 + c * 16,
                           src + (size_t)(bn + r) * K + k0 + c * 8);
            }
        }
        CP_COMMIT();
    };

    float acc[4][8][4];
#pragma unroll
    for (int m = 0; m < 4; m++)
#pragma unroll
        for (int n = 0; n < 8; n++)
#pragma unroll
            for (int k = 0; k < 4; k++) acc[m][n][k] = 0.f;

    const int NIT = K >> 5;   // BK = 32
    load_stage(0, 0);
    load_stage(1, 32);

    for (int it = 0; it < NIT; it++) {
        if (it + 1 < NIT) asm volatile("cp.async.wait_group 1;" ::: "memory");
        else              asm volatile("cp.async.wait_group 0;" ::: "memory");
        __syncthreads();
        if (it + 2 < NIT) {
            int s = (it + 2) % NSTAGE;
            load_stage(s, (it + 2) << 5);
        }

        const char* base = sm + (it % NSTAGE) * STAGE_B;
        const __nv_bfloat16* Ahs = (const __nv_bfloat16*)base;
        const __nv_bfloat16* Als = (const __nv_bfloat16*)(base + A_SUB);
        const __nv_bfloat16* Bhs = (const __nv_bfloat16*)(base + 2 * A_SUB);
        const __nv_bfloat16* Bls = (const __nv_bfloat16*)(base + 2 * A_SUB + B_SUB);

#pragma unroll
        for (int ks = 0; ks < 32; ks += 16) {
            uint32_t bh[8][2], bl[8][2];
#pragma unroll
            for (int n = 0; n < 8; n++) {
                int nr = wn * 64 + n * 8 + g;
                bh[n][0] = *(const uint32_t*)&Bhs[nr * GPAD + ks + 2 * tg];
                bh[n][1] = *(const uint32_t*)&Bhs[nr * GPAD + ks + 8 + 2 * tg];
                bl[n][0] = *(const uint32_t*)&Bls[nr * GPAD + ks + 2 * tg];
                bl[n][1] = *(const uint32_t*)&Bls[nr * GPAD + ks + 8 + 2 * tg];
            }
#pragma unroll
            for (int m = 0; m < 4; m++) {
                int mr = wm * 64 + m * 16;
                uint32_t ah[4], al[4];
                ah[0] = *(const uint32_t*)&Ahs[(mr + g)     * GPAD + ks + 2 * tg];
                ah[1] = *(const uint32_t*)&Ahs[(mr + 8 + g) * GPAD + ks + 2 * tg];
                ah[2] = *(const uint32_t*)&Ahs[(mr + g)     * GPAD + ks + 8 + 2 * tg];
                ah[3] = *(const uint32_t*)&Ahs[(mr + 8 + g) * GPAD + ks + 8 + 2 * tg];
                al[0] = *(const uint32_t*)&Als[(mr + g)     * GPAD + ks + 2 * tg];
                al[1] = *(const uint32_t*)&Als[(mr + 8 + g) * GPAD + ks + 2 * tg];
                al[2] = *(const uint32_t*)&Als[(mr + g)     * GPAD + ks + 8 + 2 * tg];
                al[3] = *(const uint32_t*)&Als[(mr + 8 + g) * GPAD + ks + 8 + 2 * tg];
#pragma unroll
                for (int n = 0; n < 8; n++) {
                    mma16816(acc[m][n], ah, bh[n][0], bh[n][1]);
                    mma16816(acc[m][n], ah, bl[n][0], bl[n][1]);
                    mma16816(acc[m][n], al, bh[n][0], bh[n][1]);
                }
            }
        }
        __syncthreads();
    }

    if (mode == 0) {
#pragma unroll
        for (int m = 0; m < 4; m++) {
            int r0 = bm + wm * 64 + m * 16 + g;
#pragma unroll
            for (int n = 0; n < 8; n++) {
                int col = bn + wn * 64 + n * 8 + 2 * tg;
                *(float2*)&C[(size_t)r0 * N + col] =
                    make_float2(acc[m][n][0], acc[m][n][1]);
                *(float2*)&C[(size_t)(r0 + 8) * N + col] =
                    make_float2(acc[m][n][2], acc[m][n][3]);
            }
        }
    } else if (bn < QSTRIDE) {
        // ---- Q region: rope + scale + hi/lo split ----
#pragma unroll
        for (int m = 0; m < 4; m++) {
            int r0 = bm + wm * 64 + m * 16 + g;
#pragma unroll
            for (int n = 0; n < 8; n++) {
                int col = bn + wn * 64 + n * 8 + 2 * tg;
                int d = (col & 127) >> 1;
                float cA = cf[r0 * 64 + d], sA = sf[r0 * 64 + d];
                float u0 = (acc[m][n][0] * cA - acc[m][n][1] * sA) * ATT_SCALE;
                float v0 = (acc[m][n][0] * sA + acc[m][n][1] * cA) * ATT_SCALE;
                store_hilo(Qh, Ql, (size_t)r0 * QSTRIDE + col, u0, v0);
                float cB = cf[(r0 + 8) * 64 + d], sB = sf[(r0 + 8) * 64 + d];
                float u1 = (acc[m][n][2] * cB - acc[m][n][3] * sB) * ATT_SCALE;
                float v1 = (acc[m][n][2] * sB + acc[m][n][3] * cB) * ATT_SCALE;
                store_hilo(Qh, Ql, (size_t)(r0 + 8) * QSTRIDE + col, u1, v1);
            }
        }
    } else if (bn < QSTRIDE + KSTRIDE) {
        // ---- K region: rope + cache + hi/lo split ----
#pragma unroll
        for (int m = 0; m < 4; m++) {
            int r0 = bm + wm * 64 + m * 16 + g;
#pragma unroll
            for (int n = 0; n < 8; n++) {
                int colk = bn - QSTRIDE + wn * 64 + n * 8 + 2 * tg;
                int d = (colk & 127) >> 1;
                float cA = cf[r0 * 64 + d], sA = sf[r0 * 64 + d];
                float u0 = acc[m][n][0] * cA - acc[m][n][1] * sA;
                float v0 = acc[m][n][0] * sA + acc[m][n][1] * cA;
                *(float2*)&CK[(size_t)r0 * KSTRIDE + colk] = make_float2(u0, v0);
                store_hilo(Kh, Kl, (size_t)r0 * KSTRIDE + colk, u0, v0);
                float cB = cf[(r0 + 8) * 64 + d], sB = sf[(r0 + 8) * 64 + d];
                float u1 = acc[m][n][2] * cB - acc[m][n][3] * sB;
                float v1 = acc[m][n][2] * sB + acc[m][n][3] * cB;
                *(float2*)&CK[(size_t)(r0 + 8) * KSTRIDE + colk] = make_float2(u1, v1);
                store_hilo(Kh, Kl, (size_t)(r0 + 8) * KSTRIDE + colk, u1, v1);
            }
        }
    } else {
        // ---- V region: cache + hi/lo split ----
#pragma unroll
        for (int m = 0; m < 4; m++) {
            int r0 = bm + wm * 64 + m * 16 + g;
#pragma unroll
            for (int n = 0; n < 8; n++) {
                int colv = bn - QSTRIDE - KSTRIDE + wn * 64 + n * 8 + 2 * tg;
                *(float2*)&CV[(size_t)r0 * KSTRIDE + colv] =
                    make_float2(acc[m][n][0], acc[m][n][1]);
                store_hilo(Vh, Vl, (size_t)r0 * KSTRIDE + colv,
                           acc[m][n][0], acc[m][n][1]);
                *(float2*)&CV[(size_t)(r0 + 8) * KSTRIDE + colv] =
                    make_float2(acc[m][n][2], acc[m][n][3]);
                store_hilo(Vh, Vl, (size_t)(r0 + 8) * KSTRIDE + colv,
                           acc[m][n][2], acc[m][n][3]);
            }
        }
    }
}

// ==================== cache tail ============================================
__global__ void cache_tail_kernel(const float* __restrict__ cki,
                                  const float* __restrict__ cvi,
                                  float* __restrict__ cko,
                                  float* __restrict__ cvo)
{
    int idx = blockIdx.x * blockDim.x + threadIdx.x;
    if (idx >= (WINDOW - SEQLEN) * KSTRIDE) return;
    size_t off = (size_t)SEQLEN * KSTRIDE + idx;
    cko[off] = cki[off];
    cvo[off] = cvi[off];
}

// ==================== HMMA flash attention (R10-proven version) =============
#define SPAD      136
#define Q_ELEMS   (128 * SPAD)
#define KV_ELEMS  (64 * SPAD)
#define ATT_SMEM  ((2 * Q_ELEMS + 8 * KV_ELEMS) * 2)

__global__ __launch_bounds__(256, 1) void flash_mma(
    const __nv_bfloat16* __restrict__ Qhg, const __nv_bfloat16* __restrict__ Qlg,
    const __nv_bfloat16* __restrict__ Khg, const __nv_bfloat16* __restrict__ Klg,
    const __nv_bfloat16* __restrict__ Vhg, const __nv_bfloat16* __restrict__ Vlg,
    __nv_bfloat16* __restrict__ Ohg, __nv_bfloat16* __restrict__ Olg)
{
    extern __shared__ __nv_bfloat16 sb[];
    const int tid  = threadIdx.x;
    const int wid  = tid >> 5;
    const int lane = tid & 31;
    const int g    = lane >> 2;
    const int tg   = lane & 3;
    const int qb   = (int)(gridDim.x - 1 - blockIdx.x);
    const int h    = blockIdx.y;
    const int kvh  = h >> 2;
    const int q0   = qb << 7;
    const int mr   = wid << 4;

    __nv_bfloat16* Qhs = sb;
    __nv_bfloat16* Qls = sb + Q_ELEMS;
    __nv_bfloat16* KVs = sb + 2 * Q_ELEMS;
    const uint32_t sbase = smem_u32(sb);

    {
        const __nv_bfloat16* gq[2] = { Qhg, Qlg };
#pragma unroll
        for (int i = 0; i < 16; i++) {
            int id  = tid + (i << 8);
            int tsr = id >> 11, idx = id & 2047;
            int r = idx >> 4, c = idx & 15;
            cp_async16(sb + tsr * Q_ELEMS + r * SPAD + c * 8,
                       gq[tsr] + (size_t)(q0 + r) * QSTRIDE + h * HD + c * 8);
        }
        CP_COMMIT();
    }

    const int NT = 2 * qb + 2;
    const __nv_bfloat16* gkv[4] = { Khg, Klg, Vhg, Vlg };
    auto load_kv = [&](int t, int st) {
        __nv_bfloat16* base = KVs + st * 4 * KV_ELEMS;
#pragma unroll
        for (int i = 0; i < 16; i++) {
            int id  = tid + (i << 8);
            int sub = id >> 10, idx = id & 1023;
            int r = idx >> 4, c = idx & 15;
            cp_async16(base + sub * KV_ELEMS + r * SPAD + c * 8,
                       gkv[sub] + (size_t)(t * 64 + r) * KSTRIDE + kvh * HD + c * 8);
        }
        CP_COMMIT();
    };
    load_kv(0, 0);

    float m0 = -1e30f, m1 = -1e30f, l0 = 0.f, l1 = 0.f;
    float o[16][4];
#pragma unroll
    for (int n = 0; n < 16; n++)
#pragma unroll
        for (int c = 0; c < 4; c++) o[n][c] = 0.f;

    for (int t = 0; t < NT; t++) {
        if (t + 1 < NT) {
            load_kv(t + 1, (t + 1) & 1);
            asm volatile("cp.async.wait_group 1;" ::: "memory");
        } else {
            asm volatile("cp.async.wait_group 0;" ::: "memory");
        }
        __syncthreads();

        if (t * 64 <= q0 + mr + 15) {
            const __nv_bfloat16* Khs = KVs + (t & 1) * 4 * KV_ELEMS;
            const __nv_bfloat16* Kls = Khs + KV_ELEMS;
            const uint32_t vh_base = sbase +
                (uint32_t)(2 * Q_ELEMS + (t & 1) * 4 * KV_ELEMS + 2 * KV_ELEMS) * 2;
            const uint32_t vl_base = vh_base + KV_ELEMS * 2;

            float sc[8][4];
#pragma unroll
            for (int n = 0; n < 8; n++)
#pragma unroll
                for (int c = 0; c < 4; c++) sc[n][c] = 0.f;

#pragma unroll
            for (int k = 0; k < 8; k++) {
                int ks = k << 4;
                uint32_t qh[4], ql[4];
                qh[0] = *(const uint32_t*)&Qhs[(mr + g)     * SPAD + ks + 2 * tg];
                qh[1] = *(const uint32_t*)&Qhs[(mr + 8 + g) * SPAD + ks + 2 * tg];
                qh[2] = *(const uint32_t*)&Qhs[(mr + g)     * SPAD + ks + 8 + 2 * tg];
                qh[3] = *(const uint32_t*)&Qhs[(mr + 8 + g) * SPAD + ks + 8 + 2 * tg];
                ql[0] = *(const uint32_t*)&Qls[(mr + g)     * SPAD + ks + 2 * tg];
                ql[1] = *(const uint32_t*)&Qls[(mr + 8 + g) * SPAD + ks + 2 * tg];
                ql[2] = *(const uint32_t*)&Qls[(mr + g)     * SPAD + ks + 8 + 2 * tg];
                ql[3] = *(const uint32_t*)&Qls[(mr + 8 + g) * SPAD + ks + 8 + 2 * tg];
#pragma unroll
                for (int n = 0; n < 8; n++) {
                    uint32_t kh0, kh1, kl0, kl1;
                    kh0 = *(const uint32_t*)&Khs[(8 * n + g) * SPAD + ks + 2 * tg];
                    kh1 = *(const uint32_t*)&Khs[(8 * n + g) * SPAD + ks + 8 + 2 * tg];
                    kl0 = *(const uint32_t*)&Kls[(8 * n + g) * SPAD + ks + 2 * tg];
                    kl1 = *(const uint32_t*)&Kls[(8 * n + g) * SPAD + ks + 8 + 2 * tg];
                    mma16816(sc[n], qh, kh0, kh1);
                    mma16816(sc[n], qh, kl0, kl1);
                    mma16816(sc[n], ql, kh0, kh1);
                }
            }

            const int qi0 = q0 + mr + g, qi1 = qi0 + 8;
            if (t * 64 + 63 > q0 + mr) {
#pragma unroll
                for (int n = 0; n < 8; n++) {
                    int kj = t * 64 + 8 * n + 2 * tg;
                    if (kj     > qi0) sc[n][0] = -1e30f;
                    if (kj + 1 > qi0) sc[n][1] = -1e30f;
                    if (kj     > qi1) sc[n][2] = -1e30f;
                    if (kj + 1 > qi1) sc[n][3] = -1e30f;
                }
            }

            float mt0 = -1e30f, mt1 = -1e30f;
#pragma unroll
            for (int n = 0; n < 8; n++) {
                mt0 = fmaxf(mt0, fmaxf(sc[n][0], sc[n][1]));
                mt1 = fmaxf(mt1, fmaxf(sc[n][2], sc[n][3]));
            }
            mt0 = fmaxf(mt0, __shfl_xor_sync(0xffffffffu, mt0, 1));
            mt0 = fmaxf(mt0, __shfl_xor_sync(0xffffffffu, mt0, 2));
            mt1 = fmaxf(mt1, __shfl_xor_sync(0xffffffffu, mt1, 1));
            mt1 = fmaxf(mt1, __shfl_xor_sync(0xffffffffu, mt1, 2));
            float m0n = fmaxf(m0, mt0), m1n = fmaxf(m1, mt1);
            float c0 = __expf(m0 - m0n), c1 = __expf(m1 - m1n);
            float rs0 = 0.f, rs1 = 0.f;
#pragma unroll
            for (int n = 0; n < 8; n++) {
                sc[n][0] = __expf(sc[n][0] - m0n);
                sc[n][1] = __expf(sc[n][1] - m0n);
                sc[n][2] = __expf(sc[n][2] - m1n);
                sc[n][3] = __expf(sc[n][3] - m1n);
                rs0 += sc[n][0] + sc[n][1];
                rs1 += sc[n][2] + sc[n][3];
            }
            rs0 += __shfl_xor_sync(0xffffffffu, rs0, 1);
            rs0 += __shfl_xor_sync(0xffffffffu, rs0, 2);
            rs1 += __shfl_xor_sync(0xffffffffu, rs1, 1);
            rs1 += __shfl_xor_sync(0xffffffffu, rs1, 2);
            l0 = l0 * c0 + rs0;
            l1 = l1 * c1 + rs1;
            m0 = m0n; m1 = m1n;
#pragma unroll
            for (int n = 0; n < 16; n++) {
                o[n][0] *= c0; o[n][1] *= c0; o[n][2] *= c1; o[n][3] *= c1;
            }

            uint32_t ph[4][4], pl[4][4];
#pragma unroll
            for (int j = 0; j < 4; j++) {
                const float* A = sc[2 * j];
                const float* B = sc[2 * j + 1];
                float ah0 = __bfloat162float(__float2bfloat16_rn(A[0]));
                float ah1 = __bfloat162float(__float2bfloat16_rn(A[1]));
                float ah2 = __bfloat162float(__float2bfloat16_rn(A[2]));
                float ah3 = __bfloat162float(__float2bfloat16_rn(A[3]));
                float bh0 = __bfloat162float(__float2bfloat16_rn(B[0]));
                float bh1 = __bfloat162float(__float2bfloat16_rn(B[1]));
                float bh2 = __bfloat162float(__float2bfloat16_rn(B[2]));
                float bh3 = __bfloat162float(__float2bfloat16_rn(B[3]));
                ph[j][0] = pack2(ah0, ah1);
                ph[j][1] = pack2(ah2, ah3);
                ph[j][2] = pack2(bh0, bh1);
                ph[j][3] = pack2(bh2, bh3);
                pl[j][0] = pack2(A[0] - ah0, A[1] - ah1);
                pl[j][1] = pack2(A[2] - ah2, A[3] - ah3);
                pl[j][2] = pack2(B[0] - bh0, B[1] - bh1);
                pl[j][3] = pack2(B[2] - bh2, B[3] - bh3);
            }

            const uint32_t va = (uint32_t)(((lane & 15) * SPAD + ((lane >> 4) << 3)) * 2);
#pragma unroll
            for (int j = 0; j < 4; j++) {
                const uint32_t kvoff = va + (uint32_t)(16 * j * SPAD * 2);
#pragma unroll
                for (int u = 0; u < 8; u++) {
                    uint32_t vh[4], vl[4];
                    ldsm_x4_t(vh, vh_base + kvoff + u * 32);
                    ldsm_x4_t(vl, vl_base + kvoff + u * 32);
                    mma16816(o[2 * u],     ph[j], vh[0], vh[1]);
                    mma16816(o[2 * u],     ph[j], vl[0], vl[1]);
                    mma16816(o[2 * u],     pl[j], vh[0], vh[1]);
                    mma16816(o[2 * u + 1], ph[j], vh[2], vh[3]);
                    mma16816(o[2 * u + 1], ph[j], vl[2], vl[3]);
                    mma16816(o[2 * u + 1], pl[j], vh[2], vh[3]);
                }
            }
        }
        __syncthreads();
    }

    const float inv0 = 1.f / l0, inv1 = 1.f / l1;
    const int row0 = q0 + mr + g, row1 = row0 + 8;
#pragma unroll
    for (int n = 0; n < 16; n++) {
        int col = h * HD + 8 * n + 2 * tg;
        float f00 = o[n][0] * inv0, f01 = o[n][1] * inv0;
        float f10 = o[n][2] * inv1, f11 = o[n][3] * inv1;
        store_hilo(Ohg, Olg, (size_t)row0 * QSTRIDE + col, f00, f01);
        store_hilo(Ohg, Olg, (size_t)row1 * QSTRIDE + col, f10, f11);
    }
}

// ==================== launch ================================================
extern "C" void kernel_launch(void* const* d_in, const int* in_sizes, int n_in,
                              void* d_out, int out_size)
{
    (void)in_sizes; (void)n_in; (void)out_size;
    const float* x   = (const float*)d_in[0];
    const float* cf  = (const float*)d_in[1];
    const float* sf  = (const float*)d_in[2];
    const float* cki = (const float*)d_in[5];
    const float* cvi = (const float*)d_in[6];
    const float* wq  = (const float*)d_in[7];
    const float* wk  = (const float*)d_in[8];
    const float* wv  = (const float*)d_in[9];
    const float* wo  = (const float*)d_in[10];

    float* out    = (float*)d_out;
    float* out_ck = out + (size_t)SEQLEN * DIM;
    float* out_cv = out_ck + (size_t)WINDOW * KSTRIDE;

    __nv_bfloat16 *xh, *xl, *wh, *wl, *woh, *wol, *aoh, *aol;
    __nv_bfloat16 *qh, *ql, *kh, *kl, *vh, *vl;
    cudaGetSymbolAddress((void**)&xh,  g_xh);
    cudaGetSymbolAddress((void**)&xl,  g_xl);
    cudaGetSymbolAddress((void**)&wh,  g_wh);
    cudaGetSymbolAddress((void**)&wl,  g_wl);
    cudaGetSymbolAddress((void**)&woh, g_woh);
    cudaGetSymbolAddress((void**)&wol, g_wol);
    cudaGetSymbolAddress((void**)&aoh, g_aoh);
    cudaGetSymbolAddress((void**)&aol, g_aol);
    cudaGetSymbolAddress((void**)&qh,  g_qh);
    cudaGetSymbolAddress((void**)&ql,  g_ql);
    cudaGetSymbolAddress((void**)&kh,  g_kh);
    cudaGetSymbolAddress((void**)&kl,  g_kl);
    cudaGetSymbolAddress((void**)&vh,  g_vh);
    cudaGetSymbolAddress((void**)&vl,  g_vl);

    cudaFuncSetAttribute(gemm_fused,
                         cudaFuncAttributeMaxDynamicSharedMemorySize, GSMEM_BYTES);
    cudaFuncSetAttribute(flash_mma,
                         cudaFuncAttributeMaxDynamicSharedMemorySize, ATT_SMEM);

    // merged splits: x, wq|wk|wv (packed), wo
    split_all_kernel<<<(SPLIT_TOTAL + 255) / 256, 256>>>(
        x, wq, wk, wv, wo, xh, xl, wh, wl, woh, wol);

    // fused QKV projection + rope + split + cache head (CTA tile 128x256)
    gemm_fused<<<dim3(NQKV / 256, SEQLEN / 128), 256, GSMEM_BYTES>>>(
        xh, xl, wh, wl, nullptr, cf, sf,
        qh, ql, kh, kl, vh, vl, out_ck, out_cv, NQKV, DIM, 1);

    cache_tail_kernel<<<((WINDOW - SEQLEN) * KSTRIDE) / 256, 256>>>(cki, cvi, out_ck, out_cv);

    // flash attention (R10-proven)
    flash_mma<<<dim3(SEQLEN / 128, NHEADS), 256, ATT_SMEM>>>(qh, ql, kh, kl, vh, vl, aoh, aol);

    // output projection
    gemm_fused<<<dim3(DIM / 256, SEQLEN / 128), 256, GSMEM_BYTES>>>(
        aoh, aol, woh, wol, out, nullptr, nullptr,
        nullptr, nullptr, nullptr, nullptr, nullptr, nullptr,
        nullptr, nullptr, DIM, DIM, 0);
}

// round 16
// speedup vs baseline: 1.7845x; 1.0161x over previous
#include <cuda_runtime.h>
#include <cuda_bf16.h>
#include <cstdint>
#include <math.h>

#define SEQLEN   2048
#define DIM      4096
#define NHEADS   32
#define NKV      8
#define HD       128
#define WINDOW   4096
#define QSTRIDE  (NHEADS * HD)   // 4096
#define KSTRIDE  (NKV * HD)      // 1024
#define NQKV     (QSTRIDE + 2 * KSTRIDE)   // 6144
#define ATT_SCALE 0.08838834764831843f

// ==================== scratch ==============================================
__device__ __nv_bfloat16 g_xh [(size_t)SEQLEN * DIM];
__device__ __nv_bfloat16 g_xl [(size_t)SEQLEN * DIM];
__device__ __nv_bfloat16 g_wh [(size_t)NQKV * DIM];     // wq|wk|wv packed
__device__ __nv_bfloat16 g_wl [(size_t)NQKV * DIM];
__device__ __nv_bfloat16 g_woh[(size_t)DIM * QSTRIDE];
__device__ __nv_bfloat16 g_wol[(size_t)DIM * QSTRIDE];
__device__ __nv_bfloat16 g_aoh[(size_t)SEQLEN * QSTRIDE];
__device__ __nv_bfloat16 g_aol[(size_t)SEQLEN * QSTRIDE];
__device__ __nv_bfloat16 g_qh[(size_t)SEQLEN * QSTRIDE];
__device__ __nv_bfloat16 g_ql[(size_t)SEQLEN * QSTRIDE];
__device__ __nv_bfloat16 g_kh[(size_t)SEQLEN * KSTRIDE];
__device__ __nv_bfloat16 g_kl[(size_t)SEQLEN * KSTRIDE];
__device__ __nv_bfloat16 g_vh[(size_t)SEQLEN * KSTRIDE];
__device__ __nv_bfloat16 g_vl[(size_t)SEQLEN * KSTRIDE];

// ==================== helpers ===============================================
__device__ __forceinline__ void mma16816(float* c, const uint32_t* a,
                                         uint32_t b0, uint32_t b1) {
    asm volatile(
        "mma.sync.aligned.m16n8k16.row.col.f32.bf16.bf16.f32 "
        "{%0,%1,%2,%3}, {%4,%5,%6,%7}, {%8,%9}, {%0,%1,%2,%3};"
        : "+f"(c[0]), "+f"(c[1]), "+f"(c[2]), "+f"(c[3])
        : "r"(a[0]), "r"(a[1]), "r"(a[2]), "r"(a[3]), "r"(b0), "r"(b1));
}
__device__ __forceinline__ void cp_async16(void* smem_dst, const void* gmem_src) {
    uint32_t sa;
    asm("{ .reg .u64 t; cvta.to.shared.u64 t, %1; cvt.u32.u64 %0, t; }"
        : "=r"(sa) : "l"(smem_dst));
    asm volatile("cp.async.cg.shared.global [%0], [%1], 16;" :: "r"(sa), "l"(gmem_src));
}
#define CP_COMMIT() asm volatile("cp.async.commit_group;" ::: "memory")
__device__ __forceinline__ void ldsm_x4_t(uint32_t* r, uint32_t addr) {
    asm volatile("ldmatrix.sync.aligned.m8n8.x4.trans.shared.b16 {%0,%1,%2,%3}, [%4];"
        : "=r"(r[0]), "=r"(r[1]), "=r"(r[2]), "=r"(r[3]) : "r"(addr));
}
__device__ __forceinline__ uint32_t smem_u32(const void* p) {
    uint32_t a;
    asm("{ .reg .u64 t; cvta.to.shared.u64 t, %1; cvt.u32.u64 %0, t; }"
        : "=r"(a) : "l"(p));
    return a;
}
__device__ __forceinline__ uint32_t pack2(float a, float b) {
    __nv_bfloat162 t = __floats2bfloat162_rn(a, b);
    return *(uint32_t*)&t;
}
__device__ __forceinline__ void store_hilo(__nv_bfloat16* H, __nv_bfloat16* L,
                                           size_t off, float a, float b) {
    float ha = __bfloat162float(__float2bfloat16_rn(a));
    float hb = __bfloat162float(__float2bfloat16_rn(b));
    *(uint32_t*)&H[off] = pack2(ha, hb);
    *(uint32_t*)&L[off] = pack2(a - ha, b - hb);
}

// ==================== merged fp32 -> bf16 hi/lo split (all tensors) =========
#define SPLIT_R0 1048576u                     // x
#define SPLIT_R1 (SPLIT_R0 + 2097152u)        // wq
#define SPLIT_R2 (SPLIT_R1 + 524288u)         // wk
#define SPLIT_R3 (SPLIT_R2 + 524288u)         // wv
#define SPLIT_R4 (SPLIT_R3 + 2097152u)        // wo
#define SPLIT_TOTAL SPLIT_R4

__global__ void split_all_kernel(const float* __restrict__ x,
                                 const float* __restrict__ wq,
                                 const float* __restrict__ wk,
                                 const float* __restrict__ wv,
                                 const float* __restrict__ wo,
                                 __nv_bfloat16* __restrict__ xh, __nv_bfloat16* __restrict__ xl,
                                 __nv_bfloat16* __restrict__ wh, __nv_bfloat16* __restrict__ wl,
                                 __nv_bfloat16* __restrict__ woh, __nv_bfloat16* __restrict__ wol)
{
    uint32_t i = blockIdx.x * blockDim.x + threadIdx.x;
    if (i >= SPLIT_TOTAL) return;

    const float* src;
    __nv_bfloat16 *hi, *lo;
    uint32_t j;
    if (i < SPLIT_R0)      { src = x;  hi = xh;  lo = xl;  j = i; }
    else if (i < SPLIT_R1) { src = wq; hi = wh;  lo = wl;  j = i - SPLIT_R0; }
    else if (i < SPLIT_R2) { src = wk; hi = wh + (size_t)QSTRIDE * DIM;
                             lo = wl + (size_t)QSTRIDE * DIM; j = i - SPLIT_R1; }
    else if (i < SPLIT_R3) { src = wv; hi = wh + (size_t)(QSTRIDE + KSTRIDE) * DIM;
                             lo = wl + (size_t)(QSTRIDE + KSTRIDE) * DIM; j = i - SPLIT_R2; }
    else                   { src = wo; hi = woh; lo = wol; j = i - SPLIT_R3; }

    float4 v0 = ((const float4*)src)[2 * (size_t)j];
    float4 v1 = ((const float4*)src)[2 * (size_t)j + 1];
    float f[8] = { v0.x, v0.y, v0.z, v0.w, v1.x, v1.y, v1.z, v1.w };
    uint32_t hw[4], lw[4];
#pragma unroll
    for (int k = 0; k < 4; k++) {
        float h0 = __bfloat162float(__float2bfloat16_rn(f[2 * k]));
        float h1 = __bfloat162float(__float2bfloat16_rn(f[2 * k + 1]));
        hw[k] = pack2(h0, h1);
        lw[k] = pack2(f[2 * k] - h0, f[2 * k + 1] - h1);
    }
    ((uint4*)hi)[j] = make_uint4(hw[0], hw[1], hw[2], hw[3]);
    ((uint4*)lo)[j] = make_uint4(lw[0], lw[1], lw[2], lw[3]);
}

// ==================== HMMA bf16x3 GEMM (R13-proven: 64x64 tile, 2-stage) ====
#define GPAD     40
#define A_SUB    10240                 // 128 rows x 80 B
#define B_SUB    20480                 // 256 rows x 80 B
#define STAGE_B  (2 * A_SUB + 2 * B_SUB)   // 61440
#define GSMEM_BYTES (2 * STAGE_B)          // 122880

__global__ __launch_bounds__(256, 1) void gemm_fused(
    const __nv_bfloat16* __restrict__ Ah, const __nv_bfloat16* __restrict__ Al,
    const __nv_bfloat16* __restrict__ Bh, const __nv_bfloat16* __restrict__ Bl,
    float* __restrict__ C,
    const float* __restrict__ cf, const float* __restrict__ sf,
    __nv_bfloat16* __restrict__ Qh, __nv_bfloat16* __restrict__ Ql,
    __nv_bfloat16* __restrict__ Kh, __nv_bfloat16* __restrict__ Kl,
    __nv_bfloat16* __restrict__ Vh, __nv_bfloat16* __restrict__ Vl,
    float* __restrict__ CK, float* __restrict__ CV,
    int N, int K, int mode)
{
    extern __shared__ char sm[];
    const int tid  = threadIdx.x;
    const int wid  = tid >> 5;
    const int lane = tid & 31;
    const int g    = lane >> 2;
    const int tg   = lane & 3;
    const int wm   = wid & 1;
    const int wn   = wid >> 1;
    const int bm   = blockIdx.y << 7;
    const int bn   = blockIdx.x << 8;

    auto load_stage = [&](int s, int k0) {
        char* base = sm + s * STAGE_B;
#pragma unroll
        for (int t = 0; t < 12; t++) {
            int id = tid + (t << 8);
            if (id < 1024) {
                int sub = id >> 9;
                int idx = id & 511;
                int r = idx >> 2, c = idx & 3;
                const __nv_bfloat16* src = (sub ? Al : Ah);
                cp_async16(base + sub * A_SUB + r * 80 + c * 16,
                           src + (size_t)(bm + r) * K + k0 + c * 8);
            } else {
                int sub = (id - 1024) >> 10;
                int idx = (id - 1024) & 1023;
                int r = idx >> 2, c = idx & 3;
                const __nv_bfloat16* src = (sub ? Bl : Bh);
                cp_async16(base + 2 * A_SUB + sub * B_SUB + r * 80 + c * 16,
                           src + (size_t)(bn + r) * K + k0 + c * 8);
            }
        }
        CP_COMMIT();
    };

    float acc[4][8][4];
#pragma unroll
    for (int m = 0; m < 4; m++)
#pragma unroll
        for (int n = 0; n < 8; n++)
#pragma unroll
            for (int k = 0; k < 4; k++) acc[m][n][k] = 0.f;

    const int NIT = K >> 5;
    load_stage(0, 0);

    for (int it = 0; it < NIT; it++) {
        asm volatile("cp.async.wait_group 0;" ::: "memory");
        __syncthreads();
        if (it + 1 < NIT) load_stage((it + 1) & 1, (it + 1) << 5);

        const char* base = sm + (it & 1) * STAGE_B;
        const __nv_bfloat16* Ahs = (const __nv_bfloat16*)base;
        const __nv_bfloat16* Als = (const __nv_bfloat16*)(base + A_SUB);
        const __nv_bfloat16* Bhs = (const __nv_bfloat16*)(base + 2 * A_SUB);
        const __nv_bfloat16* Bls = (const __nv_bfloat16*)(base + 2 * A_SUB + B_SUB);

#pragma unroll
        for (int ks = 0; ks < 32; ks += 16) {
            uint32_t bh[8][2], bl[8][2];
#pragma unroll
            for (int n = 0; n < 8; n++) {
                int nr = wn * 64 + n * 8 + g;
                bh[n][0] = *(const uint32_t*)&Bhs[nr * GPAD + ks + 2 * tg];
                bh[n][1] = *(const uint32_t*)&Bhs[nr * GPAD + ks + 8 + 2 * tg];
                bl[n][0] = *(const uint32_t*)&Bls[nr * GPAD + ks + 2 * tg];
                bl[n][1] = *(const uint32_t*)&Bls[nr * GPAD + ks + 8 + 2 * tg];
            }
#pragma unroll
            for (int m = 0; m < 4; m++) {
                int mr = wm * 64 + m * 16;
                uint32_t ah[4], al[4];
                ah[0] = *(const uint32_t*)&Ahs[(mr + g)     * GPAD + ks + 2 * tg];
                ah[1] = *(const uint32_t*)&Ahs[(mr + 8 + g) * GPAD + ks + 2 * tg];
                ah[2] = *(const uint32_t*)&Ahs[(mr + g)     * GPAD + ks + 8 + 2 * tg];
                ah[3] = *(const uint32_t*)&Ahs[(mr + 8 + g) * GPAD + ks + 8 + 2 * tg];
                al[0] = *(const uint32_t*)&Als[(mr + g)     * GPAD + ks + 2 * tg];
                al[1] = *(const uint32_t*)&Als[(mr + 8 + g) * GPAD + ks + 2 * tg];
                al[2] = *(const uint32_t*)&Als[(mr + g)     * GPAD + ks + 8 + 2 * tg];
                al[3] = *(const uint32_t*)&Als[(mr + 8 + g) * GPAD + ks + 8 + 2 * tg];
#pragma unroll
                for (int n = 0; n < 8; n++) {
                    mma16816(acc[m][n], ah, bh[n][0], bh[n][1]);
                    mma16816(acc[m][n], ah, bl[n][0], bl[n][1]);
                    mma16816(acc[m][n], al, bh[n][0], bh[n][1]);
                }
            }
        }
        __syncthreads();
    }

    if (mode == 0) {
#pragma unroll
        for (int m = 0; m < 4; m++) {
            int r0 = bm + wm * 64 + m * 16 + g;
#pragma unroll
            for (int n = 0; n < 8; n++) {
                int col = bn + wn * 64 + n * 8 + 2 * tg;
                *(float2*)&C[(size_t)r0 * N + col] =
                    make_float2(acc[m][n][0], acc[m][n][1]);
                *(float2*)&C[(size_t)(r0 + 8) * N + col] =
                    make_float2(acc[m][n][2], acc[m][n][3]);
            }
        }
    } else if (bn < QSTRIDE) {
#pragma unroll
        for (int m = 0; m < 4; m++) {
            int r0 = bm + wm * 64 + m * 16 + g;
#pragma unroll
            for (int n = 0; n < 8; n++) {
                int col = bn + wn * 64 + n * 8 + 2 * tg;
                int d = (col & 127) >> 1;
                float cA = cf[r0 * 64 + d], sA = sf[r0 * 64 + d];
                float u0 = (acc[m][n][0] * cA - acc[m][n][1] * sA) * ATT_SCALE;
                float v0 = (acc[m][n][0] * sA + acc[m][n][1] * cA) * ATT_SCALE;
                store_hilo(Qh, Ql, (size_t)r0 * QSTRIDE + col, u0, v0);
                float cB = cf[(r0 + 8) * 64 + d], sB = sf[(r0 + 8) * 64 + d];
                float u1 = (acc[m][n][2] * cB - acc[m][n][3] * sB) * ATT_SCALE;
                float v1 = (acc[m][n][2] * sB + acc[m][n][3] * cB) * ATT_SCALE;
                store_hilo(Qh, Ql, (size_t)(r0 + 8) * QSTRIDE + col, u1, v1);
            }
        }
    } else if (bn < QSTRIDE + KSTRIDE) {
#pragma unroll
        for (int m = 0; m < 4; m++) {
            int r0 = bm + wm * 64 + m * 16 + g;
#pragma unroll
            for (int n = 0; n < 8; n++) {
                int colk = bn - QSTRIDE + wn * 64 + n * 8 + 2 * tg;
                int d = (colk & 127) >> 1;
                float cA = cf[r0 * 64 + d], sA = sf[r0 * 64 + d];
                float u0 = acc[m][n][0] * cA - acc[m][n][1] * sA;
                float v0 = acc[m][n][0] * sA + acc[m][n][1] * cA;
                *(float2*)&CK[(size_t)r0 * KSTRIDE + colk] = make_float2(u0, v0);
                store_hilo(Kh, Kl, (size_t)r0 * KSTRIDE + colk, u0, v0);
                float cB = cf[(r0 + 8) * 64 + d], sB = sf[(r0 + 8) * 64 + d];
                float u1 = acc[m][n][2] * cB - acc[m][n][3] * sB;
                float v1 = acc[m][n][2] * sB + acc[m][n][3] * cB;
                *(float2*)&CK[(size_t)(r0 + 8) * KSTRIDE + colk] = make_float2(u1, v1);
                store_hilo(Kh, Kl, (size_t)(r0 + 8) * KSTRIDE + colk, u1, v1);
            }
        }
    } else {
#pragma unroll
        for (int m = 0; m < 4; m++) {
            int r0 = bm + wm * 64 + m * 16 + g;
#pragma unroll
            for (int n = 0; n < 8; n++) {
                int colv = bn - QSTRIDE - KSTRIDE + wn * 64 + n * 8 + 2 * tg;
                *(float2*)&CV[(size_t)r0 * KSTRIDE + colv] =
                    make_float2(acc[m][n][0], acc[m][n][1]);
                store_hilo(Vh, Vl, (size_t)r0 * KSTRIDE + colv,
                           acc[m][n][0], acc[m][n][1]);
                *(float2*)&CV[(size_t)(r0 + 8) * KSTRIDE + colv] =
                    make_float2(acc[m][n][2], acc[m][n][3]);
                store_hilo(Vh, Vl, (size_t)(r0 + 8) * KSTRIDE + colv,
                           acc[m][n][2], acc[m][n][3]);
            }
        }
    }
}

// ==================== cache tail ============================================
__global__ void cache_tail_kernel(const float* __restrict__ cki,
                                  const float* __restrict__ cvi,
                                  float* __restrict__ cko,
                                  float* __restrict__ cvo)
{
    int idx = blockIdx.x * blockDim.x + threadIdx.x;
    if (idx >= (WINDOW - SEQLEN) * KSTRIDE) return;
    size_t off = (size_t)SEQLEN * KSTRIDE + idx;
    cko[off] = cki[off];
    cvo[off] = cvi[off];
}

// ==================== HMMA flash attention (64 q-rows, 4 warps, occ 2) ======
#define SPAD      136
#define Q_ELEMS   (64 * SPAD)
#define KV_ELEMS  (64 * SPAD)
#define ATT_SMEM  ((2 * Q_ELEMS + 4 * KV_ELEMS) * 2)   // 104448

__global__ __launch_bounds__(128, 2) void flash_mma(
    const __nv_bfloat16* __restrict__ Qhg, const __nv_bfloat16* __restrict__ Qlg,
    const __nv_bfloat16* __restrict__ Khg, const __nv_bfloat16* __restrict__ Klg,
    const __nv_bfloat16* __restrict__ Vhg, const __nv_bfloat16* __restrict__ Vlg,
    __nv_bfloat16* __restrict__ Ohg, __nv_bfloat16* __restrict__ Olg)
{
    extern __shared__ __nv_bfloat16 sb[];
    const int tid  = threadIdx.x;
    const int wid  = tid >> 5;
    const int lane = tid & 31;
    const int g    = lane >> 2;
    const int tg   = lane & 3;
    const int qb   = (int)(gridDim.x - 1 - blockIdx.x);   // heavy first
    const int h    = blockIdx.y;
    const int kvh  = h >> 2;
    const int q0   = qb << 6;        // 64 q-rows per CTA
    const int mr   = wid << 4;       // 4 warps x 16 rows

    __nv_bfloat16* Qhs = sb;
    __nv_bfloat16* Qls = sb + Q_ELEMS;
    __nv_bfloat16* KVs = sb + 2 * Q_ELEMS;   // Kh | Kl | Vh | Vl (single buffer)
    const uint32_t sbase = smem_u32(sb);

    // ---- stage Q (hi + lo): 2 subtiles x 64 rows x 16 chunks ----
    {
        const __nv_bfloat16* gq[2] = { Qhg, Qlg };
#pragma unroll
        for (int i = 0; i < 16; i++) {
            int id  = tid + (i << 7);        // 0..2047
            int tsr = id >> 10, idx = id & 1023;
            int r = idx >> 4, c = idx & 15;
            cp_async16(sb + tsr * Q_ELEMS + r * SPAD + c * 8,
                       gq[tsr] + (size_t)(q0 + r) * QSTRIDE + h * HD + c * 8);
        }
        CP_COMMIT();
    }

    const int NT = qb + 1;
    const __nv_bfloat16* gkv[4] = { Khg, Klg, Vhg, Vlg };
    auto load_kv = [&](int t) {
#pragma unroll
        for (int i = 0; i < 32; i++) {
            int id  = tid + (i << 7);        // 0..4095
            int sub = id >> 10, idx = id & 1023;
            int r = idx >> 4, c = idx & 15;
            cp_async16(KVs + sub * KV_ELEMS + r * SPAD + c * 8,
                       gkv[sub] + (size_t)(t * 64 + r) * KSTRIDE + kvh * HD + c * 8);
        }
        CP_COMMIT();
    };
    load_kv(0);
    asm volatile("cp.async.wait_group 0;" ::: "memory");
    __syncthreads();

    float m0 = -1e30f, m1 = -1e30f, l0 = 0.f, l1 = 0.f;
    float o[16][4];
#pragma unroll
    for (int n = 0; n < 16; n++)
#pragma unroll
        for (int c = 0; c < 4; c++) o[n][c] = 0.f;

    for (int t = 0; t < NT; t++) {
        {
            const __nv_bfloat16* Khs = KVs;
            const __nv_bfloat16* Kls = KVs + KV_ELEMS;
            const uint32_t vh_base = sbase + (uint32_t)(2 * Q_ELEMS + 2 * KV_ELEMS) * 2;
            const uint32_t vl_base = vh_base + KV_ELEMS * 2;

            // ---- S = Q K^T (bf16x3) ----
            float sc[8][4];
#pragma unroll
            for (int n = 0; n < 8; n++)
#pragma unroll
                for (int c = 0; c < 4; c++) sc[n][c] = 0.f;

#pragma unroll
            for (int k = 0; k < 8; k++) {
                int ks = k << 4;
                uint32_t qh[4], ql[4];
                qh[0] = *(const uint32_t*)&Qhs[(mr + g)     * SPAD + ks + 2 * tg];
                qh[1] = *(const uint32_t*)&Qhs[(mr + 8 + g) * SPAD + ks + 2 * tg];
                qh[2] = *(const uint32_t*)&Qhs[(mr + g)     * SPAD + ks + 8 + 2 * tg];
                qh[3] = *(const uint32_t*)&Qhs[(mr + 8 + g) * SPAD + ks + 8 + 2 * tg];
                ql[0] = *(const uint32_t*)&Qls[(mr + g)     * SPAD + ks + 2 * tg];
                ql[1] = *(const uint32_t*)&Qls[(mr + 8 + g) * SPAD + ks + 2 * tg];
                ql[2] = *(const uint32_t*)&Qls[(mr + g)     * SPAD + ks + 8 + 2 * tg];
                ql[3] = *(const uint32_t*)&Qls[(mr + 8 + g) * SPAD + ks + 8 + 2 * tg];
#pragma unroll
                for (int n = 0; n < 8; n++) {
                    uint32_t kh0, kh1, kl0, kl1;
                    kh0 = *(const uint32_t*)&Khs[(8 * n + g) * SPAD + ks + 2 * tg];
                    kh1 = *(const uint32_t*)&Khs[(8 * n + g) * SPAD + ks + 8 + 2 * tg];
                    kl0 = *(const uint32_t*)&Kls[(8 * n + g) * SPAD + ks + 2 * tg];
                    kl1 = *(const uint32_t*)&Kls[(8 * n + g) * SPAD + ks + 8 + 2 * tg];
                    mma16816(sc[n], qh, kh0, kh1);
                    mma16816(sc[n], qh, kl0, kl1);
                    mma16816(sc[n], ql, kh0, kh1);
                }
            }

            // ---- causal mask (diagonal tile only) ----
            const int qi0 = q0 + mr + g, qi1 = qi0 + 8;
            if (t * 64 + 63 > q0 + mr) {
#pragma unroll
                for (int n = 0; n < 8; n++) {
                    int kj = t * 64 + 8 * n + 2 * tg;
                    if (kj     > qi0) sc[n][0] = -1e30f;
                    if (kj + 1 > qi0) sc[n][1] = -1e30f;
                    if (kj     > qi1) sc[n][2] = -1e30f;
                    if (kj + 1 > qi1) sc[n][3] = -1e30f;
                }
            }

            // ---- online softmax ----
            float mt0 = -1e30f, mt1 = -1e30f;
#pragma unroll
            for (int n = 0; n < 8; n++) {
                mt0 = fmaxf(mt0, fmaxf(sc[n][0], sc[n][1]));
                mt1 = fmaxf(mt1, fmaxf(sc[n][2], sc[n][3]));
            }
            mt0 = fmaxf(mt0, __shfl_xor_sync(0xffffffffu, mt0, 1));
            mt0 = fmaxf(mt0, __shfl_xor_sync(0xffffffffu, mt0, 2));
            mt1 = fmaxf(mt1, __shfl_xor_sync(0xffffffffu, mt1, 1));
            mt1 = fmaxf(mt1, __shfl_xor_sync(0xffffffffu, mt1, 2));
            float m0n = fmaxf(m0, mt0), m1n = fmaxf(m1, mt1);
            float c0 = __expf(m0 - m0n), c1 = __expf(m1 - m1n);
            float rs0 = 0.f, rs1 = 0.f;
#pragma unroll
            for (int n = 0; n < 8; n++) {
                sc[n][0] = __expf(sc[n][0] - m0n);
                sc[n][1] = __expf(sc[n][1] - m0n);
                sc[n][2] = __expf(sc[n][2] - m1n);
                sc[n][3] = __expf(sc[n][3] - m1n);
                rs0 += sc[n][0] + sc[n][1];
                rs1 += sc[n][2] + sc[n][3];
            }
            rs0 += __shfl_xor_sync(0xffffffffu, rs0, 1);
            rs0 += __shfl_xor_sync(0xffffffffu, rs0, 2);
            rs1 += __shfl_xor_sync(0xffffffffu, rs1, 1);
            rs1 += __shfl_xor_sync(0xffffffffu, rs1, 2);
            l0 = l0 * c0 + rs0;
            l1 = l1 * c1 + rs1;
            m0 = m0n; m1 = m1n;
#pragma unroll
            for (int n = 0; n < 16; n++) {
                o[n][0] *= c0; o[n][1] *= c0; o[n][2] *= c1; o[n][3] *= c1;
            }

            // ---- P -> bf16 hi/lo A-fragments ----
            uint32_t ph[4][4], pl[4][4];
#pragma unroll
            for (int j = 0; j < 4; j++) {
                const float* A = sc[2 * j];
                const float* B = sc[2 * j + 1];
                float ah0 = __bfloat162float(__float2bfloat16_rn(A[0]));
                float ah1 = __bfloat162float(__float2bfloat16_rn(A[1]));
                float ah2 = __bfloat162float(__float2bfloat16_rn(A[2]));
                float ah3 = __bfloat162float(__float2bfloat16_rn(A[3]));
                float bh0 = __bfloat162float(__float2bfloat16_rn(B[0]));
                float bh1 = __bfloat162float(__float2bfloat16_rn(B[1]));
                float bh2 = __bfloat162float(__float2bfloat16_rn(B[2]));
                float bh3 = __bfloat162float(__float2bfloat16_rn(B[3]));
                ph[j][0] = pack2(ah0, ah1);
                ph[j][1] = pack2(ah2, ah3);
                ph[j][2] = pack2(bh0, bh1);
                ph[j][3] = pack2(bh2, bh3);
                pl[j][0] = pack2(A[0] - ah0, A[1] - ah1);
                pl[j][1] = pack2(A[2] - ah2, A[3] - ah3);
                pl[j][2] = pack2(B[0] - bh0, B[1] - bh1);
                pl[j][3] = pack2(B[2] - bh2, B[3] - bh3);
            }

            // ---- O += P V ----
            const uint32_t va = (uint32_t)(((lane & 15) * SPAD + ((lane >> 4) << 3)) * 2);
#pragma unroll
            for (int j = 0; j < 4; j++) {
                const uint32_t kvoff = va + (uint32_t)(16 * j * SPAD * 2);
#pragma unroll
                for (int u = 0; u < 8; u++) {
                    uint32_t vh[4], vl[4];
                    ldsm_x4_t(vh, vh_base + kvoff + u * 32);
                    ldsm_x4_t(vl, vl_base + kvoff + u * 32);
                    mma16816(o[2 * u],     ph[j], vh[0], vh[1]);
                    mma16816(o[2 * u],     ph[j], vl[0], vl[1]);
                    mma16816(o[2 * u],     pl[j], vh[0], vh[1]);
                    mma16816(o[2 * u + 1], ph[j], vh[2], vh[3]);
                    mma16816(o[2 * u + 1], ph[j], vl[2], vl[3]);
                    mma16816(o[2 * u + 1], pl[j], vh[2], vh[3]);
                }
            }
        }

        if (t + 1 < NT) {
            __syncthreads();                 // all warps done reading KV
            load_kv(t + 1);
            asm volatile("cp.async.wait_group 0;" ::: "memory");
            __syncthreads();                 // KV tile visible to all
        }
    }

    // ---- epilogue: normalize, split hi/lo, store bf16 ----
    const float inv0 = 1.f / l0, inv1 = 1.f / l1;
    const int row0 = q0 + mr + g, row1 = row0 + 8;
#pragma unroll
    for (int n = 0; n < 16; n++) {
        int col = h * HD + 8 * n + 2 * tg;
        float f00 = o[n][0] * inv0, f01 = o[n][1] * inv0;
        float f10 = o[n][2] * inv1, f11 = o[n][3] * inv1;
        store_hilo(Ohg, Olg, (size_t)row0 * QSTRIDE + col, f00, f01);
        store_hilo(Ohg, Olg, (size_t)row1 * QSTRIDE + col, f10, f11);
    }
}

// ==================== launch ================================================
extern "C" void kernel_launch(void* const* d_in, const int* in_sizes, int n_in,
                              void* d_out, int out_size)
{
    (void)in_sizes; (void)n_in; (void)out_size;
    const float* x   = (const float*)d_in[0];
    const float* cf  = (const float*)d_in[1];
    const float* sf  = (const float*)d_in[2];
    const float* cki = (const float*)d_in[5];
    const float* cvi = (const float*)d_in[6];
    const float* wq  = (const float*)d_in[7];
    const float* wk  = (const float*)d_in[8];
    const float* wv  = (const float*)d_in[9];
    const float* wo  = (const float*)d_in[10];

    float* out    = (float*)d_out;
    float* out_ck = out + (size_t)SEQLEN * DIM;
    float* out_cv = out_ck + (size_t)WINDOW * KSTRIDE;

    __nv_bfloat16 *xh, *xl, *wh, *wl, *woh, *wol, *aoh, *aol;
    __nv_bfloat16 *qh, *ql, *kh, *kl, *vh, *vl;
    cudaGetSymbolAddress((void**)&xh,  g_xh);
    cudaGetSymbolAddress((void**)&xl,  g_xl);
    cudaGetSymbolAddress((void**)&wh,  g_wh);
    cudaGetSymbolAddress((void**)&wl,  g_wl);
    cudaGetSymbolAddress((void**)&woh, g_woh);
    cudaGetSymbolAddress((void**)&wol, g_wol);
    cudaGetSymbolAddress((void**)&aoh, g_aoh);
    cudaGetSymbolAddress((void**)&aol, g_aol);
    cudaGetSymbolAddress((void**)&qh,  g_qh);
    cudaGetSymbolAddress((void**)&ql,  g_ql);
    cudaGetSymbolAddress((void**)&kh,  g_kh);
    cudaGetSymbolAddress((void**)&kl,  g_kl);
    cudaGetSymbolAddress((void**)&vh,  g_vh);
    cudaGetSymbolAddress((void**)&vl,  g_vl);

    cudaFuncSetAttribute(gemm_fused,
                         cudaFuncAttributeMaxDynamicSharedMemorySize, GSMEM_BYTES);
    cudaFuncSetAttribute(flash_mma,
                         cudaFuncAttributeMaxDynamicSharedMemorySize, ATT_SMEM);

    // merged splits: x, wq|wk|wv (packed), wo
    split_all_kernel<<<(SPLIT_TOTAL + 255) / 256, 256>>>(
        x, wq, wk, wv, wo, xh, xl, wh, wl, woh, wol);

    // fused QKV projection + rope + split + cache head (CTA tile 128x256)
    gemm_fused<<<dim3(NQKV / 256, SEQLEN / 128), 256, GSMEM_BYTES>>>(
        xh, xl, wh, wl, nullptr, cf, sf,
        qh, ql, kh, kl, vh, vl, out_ck, out_cv, NQKV, DIM, 1);

    cache_tail_kernel<<<((WINDOW - SEQLEN) * KSTRIDE) / 256, 256>>>(cki, cvi, out_ck, out_cv);

    // flash attention (64 q-rows/CTA, 4 warps, 2 CTAs/SM)
    flash_mma<<<dim3(SEQLEN / 64, NHEADS), 128, ATT_SMEM>>>(qh, ql, kh, kl, vh, vl, aoh, aol);

    // output projection
    gemm_fused<<<dim3(DIM / 256, SEQLEN / 128), 256, GSMEM_BYTES>>>(
        aoh, aol, woh, wol, out, nullptr, nullptr,
        nullptr, nullptr, nullptr, nullptr, nullptr, nullptr,
        nullptr, nullptr, DIM, DIM, 0);
}